// round 16
// baseline (speedup 1.0000x reference)
#include <cuda_runtime.h>
#include <cuda_bf16.h>
#include <mma.h>
#include <math.h>
#include <stdint.h>

using namespace nvcuda;

#define BB 16
#define NN 128
#define MM 64
#define DD 512
#define HH 4
#define KK 128
#define LL 3
#define AT_NB 16

// ---------------- scratch (device globals; no allocation allowed) ----------
__device__ float d_w[BB * NN * DD];      // word projection  [B,N,D]
__device__ float d_r[BB * MM * DD];      // rel projection   [B,M,D]
__device__ float d_v[HH * DD];           // 0.5 * lin_w . score_w  [H,D]
__device__ float d_c[HH];                // lin_b . score_w + score_b
__device__ float d_G[BB * HH * DD];      // mean_n sum_m wts*had  [B,H,D]
__device__ float d_Wsum[BB * HH];        // mean_n sum_m wts      [B,H]
__device__ float d_head[BB * DD];        // concat heads          [B,D]
__device__ float d_o2[BB * DD];          // final proj pre-relu   [B,D]

// bf16 hi/lo splits: A = [word(2048) ; rel(1024)] x 512, W = [2][512][512]
__device__ __nv_bfloat16 d_Ah[3072 * 512];
__device__ __nv_bfloat16 d_Al[3072 * 512];
__device__ __nv_bfloat16 d_Bh[2 * 512 * 512];
__device__ __nv_bfloat16 d_Bl[2 * 512 * 512];

typedef unsigned long long u64;

__device__ __forceinline__ void fma2(u64& d, u64 a, u64 b) {
    asm("fma.rn.f32x2 %0, %1, %2, %3;" : "=l"(d) : "l"(a), "l"(b), "l"(d));
}
__device__ __forceinline__ u64 mul2(u64 a, u64 b) {
    u64 d;
    asm("mul.rn.f32x2 %0, %1, %2;" : "=l"(d) : "l"(a), "l"(b));
    return d;
}
__device__ __forceinline__ u64 add2(u64 a, u64 b) {
    u64 d;
    asm("add.rn.f32x2 %0, %1, %2;" : "=l"(d) : "l"(a), "l"(b));
    return d;
}
// 2*relu(x) per packed fp32 lane: x + |x|
__device__ __forceinline__ u64 relu2x(u64 p) {
    return add2(p, p & 0x7fffffff7fffffffULL);
}
__device__ __forceinline__ u64 pk(float x, float y) {
    u64 r;
    asm("mov.b64 %0, {%1, %2};" : "=l"(r) : "f"(x), "f"(y));
    return r;
}
__device__ __forceinline__ float2 upk(u64 v) {
    float2 r;
    asm("mov.b64 {%0, %1}, %2;" : "=f"(r.x), "=f"(r.y) : "l"(v));
    return r;
}
__device__ __forceinline__ uint32_t smem_u32(const void* p) {
    uint32_t a;
    asm("{ .reg .u64 t; cvta.to.shared.u64 t, %1; cvt.u32.u64 %0, t; }"
        : "=r"(a) : "l"(p));
    return a;
}
__device__ __forceinline__ void cp16(uint32_t dst, const void* src) {
    asm volatile("cp.async.ca.shared.global [%0], [%1], 16;"
                 :: "r"(dst), "l"(src) : "memory");
}
#define CP_COMMIT() asm volatile("cp.async.commit_group;" ::: "memory")
template <int N>
__device__ __forceinline__ void cp_wait() {
    asm volatile("cp.async.wait_group %0;" :: "n"(N) : "memory");
}

// ---------------- kernel 0: fused bf16 split + v/c + accumulator init ------
__global__ __launch_bounds__(256) void conv_init_kernel(
    const float* __restrict__ word, const float* __restrict__ rel,
    const float* __restrict__ Wn_w, const float* __restrict__ Wr_w,
    const float* __restrict__ lin_w, const float* __restrict__ lin_b,
    const float* __restrict__ score_w, const float* __restrict__ score_b,
    const float* __restrict__ final_b) {
    const int gid = blockIdx.x * blockDim.x + threadIdx.x;  // 192*256 = 49152
    const int NT = 192 * 256;
    for (int i = gid; i < 3072 * 512 / 4; i += NT) {
        float4 v = (i < 2048 * 512 / 4)
                       ? ((const float4*)word)[i]
                       : ((const float4*)rel)[i - 2048 * 512 / 4];
        float xs[4] = {v.x, v.y, v.z, v.w};
        __nv_bfloat16 h[4], l[4];
#pragma unroll
        for (int j = 0; j < 4; j++) {
            h[j] = __float2bfloat16(xs[j]);
            l[j] = __float2bfloat16(xs[j] - __bfloat162float(h[j]));
        }
        ((__nv_bfloat162*)d_Ah)[2 * i]     = __nv_bfloat162(h[0], h[1]);
        ((__nv_bfloat162*)d_Ah)[2 * i + 1] = __nv_bfloat162(h[2], h[3]);
        ((__nv_bfloat162*)d_Al)[2 * i]     = __nv_bfloat162(l[0], l[1]);
        ((__nv_bfloat162*)d_Al)[2 * i + 1] = __nv_bfloat162(l[2], l[3]);
    }
    for (int i = gid; i < 2 * 512 * 512 / 4; i += NT) {
        float4 v = (i < 512 * 512 / 4)
                       ? ((const float4*)Wn_w)[i]
                       : ((const float4*)Wr_w)[i - 512 * 512 / 4];
        float xs[4] = {v.x, v.y, v.z, v.w};
        __nv_bfloat16 h[4], l[4];
#pragma unroll
        for (int j = 0; j < 4; j++) {
            h[j] = __float2bfloat16(xs[j]);
            l[j] = __float2bfloat16(xs[j] - __bfloat162float(h[j]));
        }
        ((__nv_bfloat162*)d_Bh)[2 * i]     = __nv_bfloat162(h[0], h[1]);
        ((__nv_bfloat162*)d_Bh)[2 * i + 1] = __nv_bfloat162(h[2], h[3]);
        ((__nv_bfloat162*)d_Bl)[2 * i]     = __nv_bfloat162(l[0], l[1]);
        ((__nv_bfloat162*)d_Bl)[2 * i + 1] = __nv_bfloat162(l[2], l[3]);
    }
    if (gid < HH * DD) {
        int h = gid >> 9, d = gid & (DD - 1);
        const float* lp = lin_w + (h * DD + d) * KK;
        const float* sp = score_w + h * KK;
        float acc = 0.f;
#pragma unroll 8
        for (int k = 0; k < KK; k++) acc = fmaf(lp[k], sp[k], acc);
        d_v[gid] = acc * 0.5f;           // pre-scaled for x+|x| relu form
    } else if (gid < HH * DD + HH) {
        int h = gid - HH * DD;
        float acc = score_b[h];
        for (int k = 0; k < KK; k++)
            acc = fmaf(lin_b[h * KK + k], score_w[h * KK + k], acc);
        d_c[h] = acc;
    }
    for (int i = gid; i < BB * HH * DD; i += NT) d_G[i] = 0.f;
    for (int i = gid; i < BB * DD; i += NT) {
        d_head[i] = 0.f;
        d_o2[i] = final_b[i & (DD - 1)];
    }
    if (gid < BB * HH) d_Wsum[gid] = 0.f;
}

// ---------------- kernel 2: WMMA bf16-split GEMM, 64x64 tiles, 2 CTA/SM ----
#define GSM_BYTES 73728

__global__ __launch_bounds__(256, 2) void gemm_wmma_kernel(
    const float* __restrict__ Wn_b, const float* __restrict__ Wr_b) {
    extern __shared__ char gsm[];
    __nv_bfloat16* sb = (__nv_bfloat16*)gsm;
    float* Cs = (float*)gsm;
    const uint32_t smb = smem_u32(gsm);

    const int tid = threadIdx.x;
    const int wid = tid >> 5;
    const int yt = blockIdx.y;                  // 0..47 tiles of 64 rows
    const int z = (yt < 32) ? 0 : 1;
    const int arow0 = yt * 64;
    const int m0 = (z == 0) ? arow0 : arow0 - 2048;
    const int n0 = blockIdx.x * 64;
    const float* bias = (z == 0) ? Wn_b : Wr_b;
    float* C = (z == 0) ? d_w : d_r;

    const int wm = (wid >> 1) * 16;             // 4 m-subtiles of 16
    const int wn = (wid & 1) * 32;              // 2 n-subtiles of 32

    wmma::fragment<wmma::accumulator, 16, 16, 16, float> acc[2];
#pragma unroll
    for (int j = 0; j < 2; j++) wmma::fill_fragment(acc[j], 0.f);

#define GEMM_ISSUE(kt, bi)                                                    \
    {                                                                         \
        const int k0 = (kt) * 64;                                             \
        _Pragma("unroll")                                                     \
        for (int s = 0; s < 2; s++) {                                         \
            int lin = tid + s * 256;                                          \
            int row = lin >> 3, c8 = (lin & 7) * 8;                           \
            size_t goA = (size_t)(arow0 + row) * 512 + k0 + c8;               \
            uint32_t dh = smb + ((bi) * 4608 + row * 72 + c8) * 2;            \
            cp16(dh, &d_Ah[goA]);                                             \
            cp16(dh + 9216 * 2, &d_Al[goA]);                                  \
            size_t goB = (size_t)z * 512 * 512 + (size_t)(k0 + row) * 512 +   \
                         n0 + c8;                                             \
            uint32_t db = smb + (18432 + (bi) * 4608 + row * 72 + c8) * 2;    \
            cp16(db, &d_Bh[goB]);                                             \
            cp16(db + 9216 * 2, &d_Bl[goB]);                                  \
        }                                                                     \
        CP_COMMIT();                                                          \
    }

    GEMM_ISSUE(0, 0);
    for (int kt = 0; kt < 8; kt++) {
        const int bi = kt & 1;
        if (kt < 7) {
            GEMM_ISSUE(kt + 1, bi ^ 1);
            cp_wait<1>();
        } else {
            cp_wait<0>();
        }
        __syncthreads();
        const __nv_bfloat16* Ah = sb + bi * 4608;
        const __nv_bfloat16* Al = sb + 9216 + bi * 4608;
        const __nv_bfloat16* Bh = sb + 18432 + bi * 4608;
        const __nv_bfloat16* Bl = sb + 27648 + bi * 4608;
#pragma unroll
        for (int kh = 0; kh < 4; kh++) {
            wmma::fragment<wmma::matrix_a, 16, 16, 16, __nv_bfloat16,
                           wmma::row_major> ah, al;
            wmma::fragment<wmma::matrix_b, 16, 16, 16, __nv_bfloat16,
                           wmma::row_major> bh[2], bl[2];
            wmma::load_matrix_sync(ah, &Ah[wm * 72 + 16 * kh], 72);
            wmma::load_matrix_sync(al, &Al[wm * 72 + 16 * kh], 72);
#pragma unroll
            for (int j = 0; j < 2; j++) {
                wmma::load_matrix_sync(bh[j], &Bh[16 * kh * 72 + wn + 16 * j], 72);
                wmma::load_matrix_sync(bl[j], &Bl[16 * kh * 72 + wn + 16 * j], 72);
            }
#pragma unroll
            for (int j = 0; j < 2; j++) {
                wmma::mma_sync(acc[j], ah, bh[j], acc[j]);
                wmma::mma_sync(acc[j], ah, bl[j], acc[j]);
                wmma::mma_sync(acc[j], al, bh[j], acc[j]);
            }
        }
        __syncthreads();
    }
#pragma unroll
    for (int j = 0; j < 2; j++)
        wmma::store_matrix_sync(&Cs[wm * 68 + wn + 16 * j], acc[j], 68,
                                wmma::mem_row_major);
    __syncthreads();
    for (int idx = tid; idx < 64 * 16; idx += 256) {
        int row = idx >> 4, c4 = (idx & 15) * 4;
        float4 v = *(float4*)&Cs[row * 68 + c4];
        float4 bb = *(const float4*)(bias + n0 + c4);
        v.x += bb.x; v.y += bb.y; v.z += bb.z; v.w += bb.w;
        *(float4*)(C + (size_t)(m0 + row) * DD + n0 + c4) = v;
    }
}

// ---------------- kernel 3: fused attention core, 512 threads ---------------
__global__ __launch_bounds__(512, 1) void attn_kernel(const float* __restrict__ mask) {
    extern __shared__ float smf[];
    float* r_s    = smf;                          // 32768 fl
    float* w_s    = r_s + MM * DD;                // 8192 fl
    float* sw_s   = w_s + AT_NB * DD;             // 8192 fl (dup 0.5*wts)
    float* gbuf   = sw_s + AT_NB * MM * HH * 2;   // 2048 fl
    float* mask_s = gbuf + HH * DD;               // 64
    __shared__ float c_s[HH];

    const int b   = blockIdx.y;
    const int n0  = blockIdx.x * AT_NB;
    const int tid = threadIdx.x;
    const int wid = tid >> 5, lane = tid & 31;

    const float4* rg = (const float4*)(d_r + (size_t)b * MM * DD);
    float4* rs4 = (float4*)r_s;
#pragma unroll 4
    for (int i = tid; i < MM * DD / 4; i += 512) rs4[i] = rg[i];
    const float4* wg = (const float4*)(d_w + (size_t)(b * NN + n0) * DD);
    float4* ws4 = (float4*)w_s;
#pragma unroll
    for (int i = tid; i < AT_NB * DD / 4; i += 512) ws4[i] = wg[i];
    if (tid < MM) mask_s[tid] = mask[b * MM + tid];
    if (tid < HH) c_s[tid] = d_c[tid];

    // v (pre-scaled 0.5) packed: per-lane d-pairs d = 2*lane + 64*i
    u64 vr2[HH][8];
#pragma unroll
    for (int h = 0; h < HH; h++)
#pragma unroll
        for (int i = 0; i < 8; i++) {
            float2 vv = *(const float2*)&d_v[h * DD + 2 * lane + 64 * i];
            vr2[h][i] = pk(vv.x, vv.y);
        }

    __syncthreads();

    // ---- pass 1: scores -> sw_s[(nn*MM+m)*8 + 2h]; warp handles 4 m's ----
#pragma unroll 1
    for (int nn = 0; nn < AT_NB; nn++) {
        u64 w2[8];
#pragma unroll
        for (int i = 0; i < 8; i++)
            w2[i] = *(const u64*)&w_s[nn * DD + 2 * lane + 64 * i];
#pragma unroll 1
        for (int mi = 0; mi < 4; mi++) {
            int m = wid * 4 + mi;
            const float* rrow = r_s + m * DD + 2 * lane;
            u64 a0 = 0, a1 = 0, a2 = 0, a3 = 0;
#pragma unroll
            for (int i = 0; i < 8; i++) {
                u64 rv = *(const u64*)&rrow[64 * i];
                u64 hv = relu2x(mul2(w2[i], rv));   // 2*relu(w*r)
                fma2(a0, hv, vr2[0][i]);
                fma2(a1, hv, vr2[1][i]);
                fma2(a2, hv, vr2[2][i]);
                fma2(a3, hv, vr2[3][i]);
            }
            float2 A0 = upk(a0), A1 = upk(a1), A2 = upk(a2), A3 = upk(a3);
            float s0 = A0.x + A0.y, s1 = A1.x + A1.y;
            float s2 = A2.x + A2.y, s3 = A3.x + A3.y;
            // 3-stage full butterfly (bits 4,3,2)
#pragma unroll
            for (int off = 16; off >= 4; off >>= 1) {
                s0 += __shfl_xor_sync(0xffffffffu, s0, off);
                s1 += __shfl_xor_sync(0xffffffffu, s1, off);
                s2 += __shfl_xor_sync(0xffffffffu, s2, off);
                s3 += __shfl_xor_sync(0xffffffffu, s3, off);
            }
            // pairwise value-merge exchanges (bits 0,1)
            bool b0 = lane & 1, b1 = lane & 2;
            float x01 = b0 ? s1 : s0, y01 = b0 ? s0 : s1;
            x01 += __shfl_xor_sync(0xffffffffu, y01, 1);
            float x23 = b0 ? s3 : s2, y23 = b0 ? s2 : s3;
            x23 += __shfl_xor_sync(0xffffffffu, y23, 1);
            float xf = b1 ? x23 : x01, yf = b1 ? x01 : x23;
            xf += __shfl_xor_sync(0xffffffffu, yf, 2);
            if (lane < 4)
                sw_s[(nn * MM + m) * 8 + 2 * lane] = xf + c_s[lane];
        }
    }
    __syncthreads();

    // ---- softmax over m; store DUPLICATED 0.5-scaled weights ----
    for (int p = wid; p < AT_NB * HH; p += 16) {
        int nn = p >> 2, h = p & 3;
        float x0 = sw_s[(nn * MM + lane) * 8 + 2 * h];
        float x1 = sw_s[(nn * MM + lane + 32) * 8 + 2 * h];
        float mx = fmaxf(x0, x1);
#pragma unroll
        for (int off = 16; off; off >>= 1)
            mx = fmaxf(mx, __shfl_xor_sync(0xffffffffu, mx, off));
        float e0 = __expf(x0 - mx), e1 = __expf(x1 - mx);
        float s = e0 + e1;
#pragma unroll
        for (int off = 16; off; off >>= 1)
            s += __shfl_xor_sync(0xffffffffu, s, off);
        float inv = 1.f / s;
        float w0 = e0 * inv * mask_s[lane];
        float w1 = e1 * inv * mask_s[lane + 32];
        float* p0 = sw_s + (nn * MM + lane) * 8 + 2 * h;
        float* p1 = sw_s + (nn * MM + lane + 32) * 8 + 2 * h;
        float h0 = w0 * 0.5f, h1 = w1 * 0.5f;
        p0[0] = h0; p0[1] = h0;
        p1[0] = h1; p1[1] = h1;
        float ws = w0 + w1;
#pragma unroll
        for (int off = 16; off; off >>= 1)
            ws += __shfl_xor_sync(0xffffffffu, ws, off);
        if (lane == 0) atomicAdd(&d_Wsum[b * HH + h], ws * (1.f / (float)NN));
    }
    __syncthreads();

    // ---- pass 2: thread = (d-pair, m-half); m outer, w[16] in registers ----
    const int dpi = tid & 255, mh = tid >> 8;
    const int dp = 2 * dpi;
    u64 wv[AT_NB];
#pragma unroll
    for (int nn = 0; nn < AT_NB; nn++)
        wv[nn] = *(const u64*)&w_s[nn * DD + dp];
    u64 g2[HH] = {0ull, 0ull, 0ull, 0ull};
#pragma unroll 1
    for (int m = mh * 32; m < mh * 32 + 32; m++) {
        u64 rv = *(const u64*)&r_s[m * DD + dp];
#pragma unroll
        for (int nn = 0; nn < AT_NB; nn++) {
            u64 hv = relu2x(mul2(wv[nn], rv));     // 2*relu(w*r)
            const float* swp = sw_s + (nn * MM + m) * 8;
            longlong2 q0 = *(const longlong2*)(swp);
            longlong2 q1 = *(const longlong2*)(swp + 4);
            fma2(g2[0], hv, (u64)q0.x);
            fma2(g2[1], hv, (u64)q0.y);
            fma2(g2[2], hv, (u64)q1.x);
            fma2(g2[3], hv, (u64)q1.y);
        }
    }
    if (mh == 1) {
#pragma unroll
        for (int h = 0; h < HH; h++) {
            float2 gv = upk(g2[h]);
            *(float2*)&gbuf[h * DD + dp] = gv;
        }
    }
    __syncthreads();
    if (mh == 0) {
#pragma unroll
        for (int h = 0; h < HH; h++) {
            float2 gv = upk(g2[h]);
            float2 ov = *(const float2*)&gbuf[h * DD + dp];
            atomicAdd(&d_G[(b * HH + h) * DD + dp + 0],
                      (gv.x + ov.x) * (1.f / (float)NN));
            atomicAdd(&d_G[(b * HH + h) * DD + dp + 1],
                      (gv.y + ov.y) * (1.f / (float)NN));
        }
    }
}

// ---------------- kernel 4: head proj, weight-reuse over batch -------------
__global__ __launch_bounds__(256) void head_kernel(
    const float* __restrict__ lin_w, const float* __restrict__ lin_b) {
    const int h = blockIdx.x, dc = blockIdx.y;
    const int d0 = dc * 16;
    const int tid = threadIdx.x;
    const int k = tid & 127, half = tid >> 7;
    __shared__ float Gs[BB][16];
    __shared__ float Ws[BB];
    if (tid < BB * 16)
        Gs[tid >> 4][tid & 15] = d_G[((tid >> 4) * HH + h) * DD + d0 + (tid & 15)];
    if (tid < BB) Ws[tid] = d_Wsum[tid * HH + h];
    __syncthreads();

    float acc[BB];
    if (dc == 0 && half == 0) {
        float lb = lin_b[h * KK + k];
#pragma unroll
        for (int b = 0; b < BB; b++) acc[b] = Ws[b] * lb;
    } else {
#pragma unroll
        for (int b = 0; b < BB; b++) acc[b] = 0.f;
    }
#pragma unroll
    for (int dd = 0; dd < 8; dd++) {
        int d = d0 + half * 8 + dd;
        float lw = lin_w[((size_t)h * DD + d) * KK + k];
#pragma unroll
        for (int b = 0; b < BB; b++)
            acc[b] = fmaf(Gs[b][half * 8 + dd], lw, acc[b]);
    }
#pragma unroll
    for (int b = 0; b < BB; b++)
        atomicAdd(&d_head[b * DD + h * KK + k], acc[b]);
}

// ---------------- kernel 5: final proj, weight-reuse over batch ------------
__global__ __launch_bounds__(256) void final_kernel(
    const float* __restrict__ final_w) {
    const int j0 = blockIdx.x * 128, i0 = blockIdx.y * 16;
    const int tid = threadIdx.x;
    const int j = j0 + (tid & 127), half = tid >> 7;
    __shared__ float hs[BB][16];
    if (tid < BB * 16)
        hs[tid >> 4][tid & 15] = d_head[(tid >> 4) * DD + i0 + (tid & 15)];
    __syncthreads();

    float acc[BB];
#pragma unroll
    for (int b = 0; b < BB; b++) acc[b] = 0.f;
#pragma unroll
    for (int ii = 0; ii < 8; ii++) {
        int i = i0 + half * 8 + ii;
        float fw = final_w[(size_t)i * DD + j];
#pragma unroll
        for (int b = 0; b < BB; b++)
            acc[b] = fmaf(hs[b][half * 8 + ii], fw, acc[b]);
    }
#pragma unroll
    for (int b = 0; b < BB; b++)
        atomicAdd(&d_o2[b * DD + j], acc[b]);
}

// ---------------- kernel 6: fc logits (relu applied on read) ---------------
__global__ __launch_bounds__(128) void fc_kernel(
    const float* __restrict__ fc_w, const float* __restrict__ fc_b,
    float* __restrict__ out) {
    const int b = blockIdx.x;
    const int tid = threadIdx.x;
    const int wid = tid >> 5, lane = tid & 31;
    __shared__ float os[DD];
    for (int i = tid; i < DD; i += 128)
        os[i] = fmaxf(d_o2[b * DD + i], 0.f);
    __syncthreads();
    if (wid < LL) {
        float acc = 0.f;
#pragma unroll 4
        for (int i = lane; i < DD; i += 32)
            acc = fmaf(os[i], fc_w[i * LL + wid], acc);
#pragma unroll
        for (int off = 16; off; off >>= 1)
            acc += __shfl_xor_sync(0xffffffffu, acc, off);
        if (lane == 0) out[b * LL + wid] = acc + fc_b[wid];
    }
}

// ---------------- launcher ---------------------------------------------------
extern "C" void kernel_launch(void* const* d_in, const int* in_sizes, int n_in,
                              void* d_out, int out_size) {
    const float* word    = (const float*)d_in[0];
    const float* rel     = (const float*)d_in[1];
    const float* mask    = (const float*)d_in[2];
    const float* Wn_w    = (const float*)d_in[3];
    const float* Wn_b    = (const float*)d_in[4];
    const float* Wr_w    = (const float*)d_in[5];
    const float* Wr_b    = (const float*)d_in[6];
    const float* lin_w   = (const float*)d_in[7];
    const float* lin_b   = (const float*)d_in[8];
    const float* score_w = (const float*)d_in[9];
    const float* score_b = (const float*)d_in[10];
    const float* final_w = (const float*)d_in[11];
    const float* final_b = (const float*)d_in[12];
    const float* fc_w    = (const float*)d_in[13];
    const float* fc_b    = (const float*)d_in[14];
    float* out = (float*)d_out;

    conv_init_kernel<<<192, 256>>>(word, rel, Wn_w, Wr_w, lin_w, lin_b,
                                   score_w, score_b, final_b);

    cudaFuncSetAttribute(gemm_wmma_kernel,
                         cudaFuncAttributeMaxDynamicSharedMemorySize, GSM_BYTES);
    gemm_wmma_kernel<<<dim3(8, 48), 256, GSM_BYTES>>>(Wn_b, Wr_b);

    const int smem_bytes =
        (MM * DD + AT_NB * DD + AT_NB * MM * HH * 2 + HH * DD + 64) * 4;
    cudaFuncSetAttribute(attn_kernel,
                         cudaFuncAttributeMaxDynamicSharedMemorySize, smem_bytes);
    attn_kernel<<<dim3(NN / AT_NB, BB), 512, smem_bytes>>>(mask);

    head_kernel<<<dim3(HH, 32), 256>>>(lin_w, lin_b);
    final_kernel<<<dim3(4, 32), 256>>>(final_w);
    fc_kernel<<<BB, 128>>>(fc_w, fc_b, out);
}

// round 17
// speedup vs baseline: 1.0191x; 1.0191x over previous
#include <cuda_runtime.h>
#include <cuda_bf16.h>
#include <mma.h>
#include <math.h>
#include <stdint.h>

using namespace nvcuda;

#define BB 16
#define NN 128
#define MM 64
#define DD 512
#define HH 4
#define KK 128
#define LL 3
#define AT_NB 16

// ---------------- scratch (device globals; no allocation allowed) ----------
__device__ float d_w[BB * NN * DD];      // word projection  [B,N,D]
__device__ float d_r[BB * MM * DD];      // rel projection   [B,M,D]
__device__ float d_v[HH * DD];           // lin_w . score_w  [H,D]
__device__ float d_c[HH];                // lin_b . score_w + score_b
__device__ float d_G[BB * HH * DD];      // mean_n sum_m wts*had  [B,H,D]
__device__ float d_Wsum[BB * HH];        // mean_n sum_m wts      [B,H]
__device__ float d_head[BB * DD];        // concat heads          [B,D]
__device__ float d_o2[BB * DD];          // final proj pre-relu   [B,D]

// bf16 hi/lo splits: A = [word(2048) ; rel(1024)] x 512, W = [2][512][512]
__device__ __nv_bfloat16 d_Ah[3072 * 512];
__device__ __nv_bfloat16 d_Al[3072 * 512];
__device__ __nv_bfloat16 d_Bh[2 * 512 * 512];
__device__ __nv_bfloat16 d_Bl[2 * 512 * 512];

typedef unsigned long long u64;

__device__ __forceinline__ void fma2(u64& d, u64 a, u64 b) {
    asm("fma.rn.f32x2 %0, %1, %2, %3;" : "=l"(d) : "l"(a), "l"(b), "l"(d));
}
__device__ __forceinline__ u64 mul2(u64 a, u64 b) {
    u64 d;
    asm("mul.rn.f32x2 %0, %1, %2;" : "=l"(d) : "l"(a), "l"(b));
    return d;
}
__device__ __forceinline__ u64 pk(float x, float y) {
    u64 r;
    asm("mov.b64 %0, {%1, %2};" : "=l"(r) : "f"(x), "f"(y));
    return r;
}
__device__ __forceinline__ float2 upk(u64 v) {
    float2 r;
    asm("mov.b64 {%0, %1}, %2;" : "=f"(r.x), "=f"(r.y) : "l"(v));
    return r;
}
__device__ __forceinline__ uint32_t smem_u32(const void* p) {
    uint32_t a;
    asm("{ .reg .u64 t; cvta.to.shared.u64 t, %1; cvt.u32.u64 %0, t; }"
        : "=r"(a) : "l"(p));
    return a;
}
__device__ __forceinline__ void cp16(uint32_t dst, const void* src) {
    asm volatile("cp.async.ca.shared.global [%0], [%1], 16;"
                 :: "r"(dst), "l"(src) : "memory");
}
#define CP_COMMIT() asm volatile("cp.async.commit_group;" ::: "memory")
template <int N>
__device__ __forceinline__ void cp_wait() {
    asm volatile("cp.async.wait_group %0;" :: "n"(N) : "memory");
}

// ---------------- kernel 0: fused bf16 split + v/c + accumulator init ------
__global__ __launch_bounds__(256) void conv_init_kernel(
    const float* __restrict__ word, const float* __restrict__ rel,
    const float* __restrict__ Wn_w, const float* __restrict__ Wr_w,
    const float* __restrict__ lin_w, const float* __restrict__ lin_b,
    const float* __restrict__ score_w, const float* __restrict__ score_b,
    const float* __restrict__ final_b) {
    const int gid = blockIdx.x * blockDim.x + threadIdx.x;  // 192*256 = 49152
    const int NT = 192 * 256;
    for (int i = gid; i < 3072 * 512 / 4; i += NT) {
        float4 v = (i < 2048 * 512 / 4)
                       ? ((const float4*)word)[i]
                       : ((const float4*)rel)[i - 2048 * 512 / 4];
        float xs[4] = {v.x, v.y, v.z, v.w};
        __nv_bfloat16 h[4], l[4];
#pragma unroll
        for (int j = 0; j < 4; j++) {
            h[j] = __float2bfloat16(xs[j]);
            l[j] = __float2bfloat16(xs[j] - __bfloat162float(h[j]));
        }
        ((__nv_bfloat162*)d_Ah)[2 * i]     = __nv_bfloat162(h[0], h[1]);
        ((__nv_bfloat162*)d_Ah)[2 * i + 1] = __nv_bfloat162(h[2], h[3]);
        ((__nv_bfloat162*)d_Al)[2 * i]     = __nv_bfloat162(l[0], l[1]);
        ((__nv_bfloat162*)d_Al)[2 * i + 1] = __nv_bfloat162(l[2], l[3]);
    }
    for (int i = gid; i < 2 * 512 * 512 / 4; i += NT) {
        float4 v = (i < 512 * 512 / 4)
                       ? ((const float4*)Wn_w)[i]
                       : ((const float4*)Wr_w)[i - 512 * 512 / 4];
        float xs[4] = {v.x, v.y, v.z, v.w};
        __nv_bfloat16 h[4], l[4];
#pragma unroll
        for (int j = 0; j < 4; j++) {
            h[j] = __float2bfloat16(xs[j]);
            l[j] = __float2bfloat16(xs[j] - __bfloat162float(h[j]));
        }
        ((__nv_bfloat162*)d_Bh)[2 * i]     = __nv_bfloat162(h[0], h[1]);
        ((__nv_bfloat162*)d_Bh)[2 * i + 1] = __nv_bfloat162(h[2], h[3]);
        ((__nv_bfloat162*)d_Bl)[2 * i]     = __nv_bfloat162(l[0], l[1]);
        ((__nv_bfloat162*)d_Bl)[2 * i + 1] = __nv_bfloat162(l[2], l[3]);
    }
    if (gid < HH * DD) {
        int h = gid >> 9, d = gid & (DD - 1);
        const float* lp = lin_w + (h * DD + d) * KK;
        const float* sp = score_w + h * KK;
        float acc = 0.f;
#pragma unroll 8
        for (int k = 0; k < KK; k++) acc = fmaf(lp[k], sp[k], acc);
        d_v[gid] = acc;
    } else if (gid < HH * DD + HH) {
        int h = gid - HH * DD;
        float acc = score_b[h];
        for (int k = 0; k < KK; k++)
            acc = fmaf(lin_b[h * KK + k], score_w[h * KK + k], acc);
        d_c[h] = acc;
    }
    for (int i = gid; i < BB * HH * DD; i += NT) d_G[i] = 0.f;
    for (int i = gid; i < BB * DD; i += NT) {
        d_head[i] = 0.f;
        d_o2[i] = final_b[i & (DD - 1)];
    }
    if (gid < BB * HH) d_Wsum[gid] = 0.f;
}

// ---------------- kernel 2: WMMA bf16-split GEMM, 64x64 tiles, 2 CTA/SM ----
#define GSM_BYTES 73728

__global__ __launch_bounds__(256, 2) void gemm_wmma_kernel(
    const float* __restrict__ Wn_b, const float* __restrict__ Wr_b) {
    extern __shared__ char gsm[];
    __nv_bfloat16* sb = (__nv_bfloat16*)gsm;
    float* Cs = (float*)gsm;
    const uint32_t smb = smem_u32(gsm);

    const int tid = threadIdx.x;
    const int wid = tid >> 5;
    const int yt = blockIdx.y;                  // 0..47 tiles of 64 rows
    const int z = (yt < 32) ? 0 : 1;
    const int arow0 = yt * 64;
    const int m0 = (z == 0) ? arow0 : arow0 - 2048;
    const int n0 = blockIdx.x * 64;
    const float* bias = (z == 0) ? Wn_b : Wr_b;
    float* C = (z == 0) ? d_w : d_r;

    const int wm = (wid >> 1) * 16;             // 4 m-subtiles of 16
    const int wn = (wid & 1) * 32;              // 2 n-subtiles of 32

    wmma::fragment<wmma::accumulator, 16, 16, 16, float> acc[2];
#pragma unroll
    for (int j = 0; j < 2; j++) wmma::fill_fragment(acc[j], 0.f);

#define GEMM_ISSUE(kt, bi)                                                    \
    {                                                                         \
        const int k0 = (kt) * 64;                                             \
        _Pragma("unroll")                                                     \
        for (int s = 0; s < 2; s++) {                                         \
            int lin = tid + s * 256;                                          \
            int row = lin >> 3, c8 = (lin & 7) * 8;                           \
            size_t goA = (size_t)(arow0 + row) * 512 + k0 + c8;               \
            uint32_t dh = smb + ((bi) * 4608 + row * 72 + c8) * 2;            \
            cp16(dh, &d_Ah[goA]);                                             \
            cp16(dh + 9216 * 2, &d_Al[goA]);                                  \
            size_t goB = (size_t)z * 512 * 512 + (size_t)(k0 + row) * 512 +   \
                         n0 + c8;                                             \
            uint32_t db = smb + (18432 + (bi) * 4608 + row * 72 + c8) * 2;    \
            cp16(db, &d_Bh[goB]);                                             \
            cp16(db + 9216 * 2, &d_Bl[goB]);                                  \
        }                                                                     \
        CP_COMMIT();                                                          \
    }

    GEMM_ISSUE(0, 0);
    for (int kt = 0; kt < 8; kt++) {
        const int bi = kt & 1;
        if (kt < 7) {
            GEMM_ISSUE(kt + 1, bi ^ 1);
            cp_wait<1>();
        } else {
            cp_wait<0>();
        }
        __syncthreads();
        const __nv_bfloat16* Ah = sb + bi * 4608;
        const __nv_bfloat16* Al = sb + 9216 + bi * 4608;
        const __nv_bfloat16* Bh = sb + 18432 + bi * 4608;
        const __nv_bfloat16* Bl = sb + 27648 + bi * 4608;
#pragma unroll
        for (int kh = 0; kh < 4; kh++) {
            wmma::fragment<wmma::matrix_a, 16, 16, 16, __nv_bfloat16,
                           wmma::row_major> ah, al;
            wmma::fragment<wmma::matrix_b, 16, 16, 16, __nv_bfloat16,
                           wmma::row_major> bh[2], bl[2];
            wmma::load_matrix_sync(ah, &Ah[wm * 72 + 16 * kh], 72);
            wmma::load_matrix_sync(al, &Al[wm * 72 + 16 * kh], 72);
#pragma unroll
            for (int j = 0; j < 2; j++) {
                wmma::load_matrix_sync(bh[j], &Bh[16 * kh * 72 + wn + 16 * j], 72);
                wmma::load_matrix_sync(bl[j], &Bl[16 * kh * 72 + wn + 16 * j], 72);
            }
#pragma unroll
            for (int j = 0; j < 2; j++) {
                wmma::mma_sync(acc[j], ah, bh[j], acc[j]);
                wmma::mma_sync(acc[j], ah, bl[j], acc[j]);
                wmma::mma_sync(acc[j], al, bh[j], acc[j]);
            }
        }
        __syncthreads();
    }
#pragma unroll
    for (int j = 0; j < 2; j++)
        wmma::store_matrix_sync(&Cs[wm * 68 + wn + 16 * j], acc[j], 68,
                                wmma::mem_row_major);
    __syncthreads();
    for (int idx = tid; idx < 64 * 16; idx += 256) {
        int row = idx >> 4, c4 = (idx & 15) * 4;
        float4 v = *(float4*)&Cs[row * 68 + c4];
        float4 bb = *(const float4*)(bias + n0 + c4);
        v.x += bb.x; v.y += bb.y; v.z += bb.z; v.w += bb.w;
        *(float4*)(C + (size_t)(m0 + row) * DD + n0 + c4) = v;
    }
}

// ---------------- kernel 3: fused attention core, 512 threads ---------------
__global__ __launch_bounds__(512, 1) void attn_kernel(const float* __restrict__ mask) {
    extern __shared__ float smf[];
    float* r_s    = smf;                          // 32768 fl
    float* w_s    = r_s + MM * DD;                // 8192 fl
    float* sw_s   = w_s + AT_NB * DD;             // 8192 fl (dup wts)
    float* gbuf   = sw_s + AT_NB * MM * HH * 2;   // 2048 fl
    float* mask_s = gbuf + HH * DD;               // 64
    __shared__ float c_s[HH];

    const int b   = blockIdx.y;
    const int n0  = blockIdx.x * AT_NB;
    const int tid = threadIdx.x;
    const int wid = tid >> 5, lane = tid & 31;

    const float4* rg = (const float4*)(d_r + (size_t)b * MM * DD);
    float4* rs4 = (float4*)r_s;
#pragma unroll 4
    for (int i = tid; i < MM * DD / 4; i += 512) rs4[i] = rg[i];
    const float4* wg = (const float4*)(d_w + (size_t)(b * NN + n0) * DD);
    float4* ws4 = (float4*)w_s;
#pragma unroll
    for (int i = tid; i < AT_NB * DD / 4; i += 512) ws4[i] = wg[i];
    if (tid < MM) mask_s[tid] = mask[b * MM + tid];
    if (tid < HH) c_s[tid] = d_c[tid];

    // v packed: per-lane d-pairs d = 2*lane + 64*i
    u64 vr2[HH][8];
#pragma unroll
    for (int h = 0; h < HH; h++)
#pragma unroll
        for (int i = 0; i < 8; i++) {
            float2 vv = *(const float2*)&d_v[h * DD + 2 * lane + 64 * i];
            vr2[h][i] = pk(vv.x, vv.y);
        }

    __syncthreads();

    // ---- pass 1: scores -> sw_s[(nn*MM+m)*8 + 2h]; warp handles 4 m's ----
    // mi unrolled x2: two independent accumulate+reduce chains per warp.
#pragma unroll 1
    for (int nn = 0; nn < AT_NB; nn++) {
        u64 w2[8];
#pragma unroll
        for (int i = 0; i < 8; i++)
            w2[i] = *(const u64*)&w_s[nn * DD + 2 * lane + 64 * i];
#pragma unroll 2
        for (int mi = 0; mi < 4; mi++) {
            int m = wid * 4 + mi;
            const float* rrow = r_s + m * DD + 2 * lane;
            u64 a0 = 0, a1 = 0, a2 = 0, a3 = 0;
#pragma unroll
            for (int i = 0; i < 8; i++) {
                u64 rv = *(const u64*)&rrow[64 * i];
                float2 p = upk(mul2(w2[i], rv));
                u64 hv = pk(fmaxf(p.x, 0.f), fmaxf(p.y, 0.f));
                fma2(a0, hv, vr2[0][i]);
                fma2(a1, hv, vr2[1][i]);
                fma2(a2, hv, vr2[2][i]);
                fma2(a3, hv, vr2[3][i]);
            }
            float2 A0 = upk(a0), A1 = upk(a1), A2 = upk(a2), A3 = upk(a3);
            float s0 = A0.x + A0.y, s1 = A1.x + A1.y;
            float s2 = A2.x + A2.y, s3 = A3.x + A3.y;
            // 3-stage full butterfly (bits 4,3,2)
#pragma unroll
            for (int off = 16; off >= 4; off >>= 1) {
                s0 += __shfl_xor_sync(0xffffffffu, s0, off);
                s1 += __shfl_xor_sync(0xffffffffu, s1, off);
                s2 += __shfl_xor_sync(0xffffffffu, s2, off);
                s3 += __shfl_xor_sync(0xffffffffu, s3, off);
            }
            // pairwise value-merge exchanges (bits 0,1)
            bool b0 = lane & 1, b1 = lane & 2;
            float x01 = b0 ? s1 : s0, y01 = b0 ? s0 : s1;
            x01 += __shfl_xor_sync(0xffffffffu, y01, 1);
            float x23 = b0 ? s3 : s2, y23 = b0 ? s2 : s3;
            x23 += __shfl_xor_sync(0xffffffffu, y23, 1);
            float xf = b1 ? x23 : x01, yf = b1 ? x01 : x23;
            xf += __shfl_xor_sync(0xffffffffu, yf, 2);
            if (lane < 4)
                sw_s[(nn * MM + m) * 8 + 2 * lane] = xf + c_s[lane];
        }
    }
    __syncthreads();

    // ---- softmax over m; store DUPLICATED weights (t,t) pairs ----
    for (int p = wid; p < AT_NB * HH; p += 16) {
        int nn = p >> 2, h = p & 3;
        float x0 = sw_s[(nn * MM + lane) * 8 + 2 * h];
        float x1 = sw_s[(nn * MM + lane + 32) * 8 + 2 * h];
        float mx = fmaxf(x0, x1);
#pragma unroll
        for (int off = 16; off; off >>= 1)
            mx = fmaxf(mx, __shfl_xor_sync(0xffffffffu, mx, off));
        float e0 = __expf(x0 - mx), e1 = __expf(x1 - mx);
        float s = e0 + e1;
#pragma unroll
        for (int off = 16; off; off >>= 1)
            s += __shfl_xor_sync(0xffffffffu, s, off);
        float inv = 1.f / s;
        float w0 = e0 * inv * mask_s[lane];
        float w1 = e1 * inv * mask_s[lane + 32];
        float* p0 = sw_s + (nn * MM + lane) * 8 + 2 * h;
        float* p1 = sw_s + (nn * MM + lane + 32) * 8 + 2 * h;
        p0[0] = w0; p0[1] = w0;
        p1[0] = w1; p1[1] = w1;
        float ws = w0 + w1;
#pragma unroll
        for (int off = 16; off; off >>= 1)
            ws += __shfl_xor_sync(0xffffffffu, ws, off);
        if (lane == 0) atomicAdd(&d_Wsum[b * HH + h], ws * (1.f / (float)NN));
    }
    __syncthreads();

    // ---- pass 2: thread = (d-pair, m-half); m outer x2, w[16] in regs ----
    const int dpi = tid & 255, mh = tid >> 8;
    const int dp = 2 * dpi;
    u64 wv[AT_NB];
#pragma unroll
    for (int nn = 0; nn < AT_NB; nn++)
        wv[nn] = *(const u64*)&w_s[nn * DD + dp];
    u64 g2[HH] = {0ull, 0ull, 0ull, 0ull};
#pragma unroll 2
    for (int m = mh * 32; m < mh * 32 + 32; m++) {
        u64 rv = *(const u64*)&r_s[m * DD + dp];
#pragma unroll
        for (int nn = 0; nn < AT_NB; nn++) {
            float2 pf = upk(mul2(wv[nn], rv));
            u64 hv = pk(fmaxf(pf.x, 0.f), fmaxf(pf.y, 0.f));
            const float* swp = sw_s + (nn * MM + m) * 8;
            longlong2 q0 = *(const longlong2*)(swp);
            longlong2 q1 = *(const longlong2*)(swp + 4);
            fma2(g2[0], hv, (u64)q0.x);
            fma2(g2[1], hv, (u64)q0.y);
            fma2(g2[2], hv, (u64)q1.x);
            fma2(g2[3], hv, (u64)q1.y);
        }
    }
    if (mh == 1) {
#pragma unroll
        for (int h = 0; h < HH; h++) {
            float2 gv = upk(g2[h]);
            *(float2*)&gbuf[h * DD + dp] = gv;
        }
    }
    __syncthreads();
    if (mh == 0) {
#pragma unroll
        for (int h = 0; h < HH; h++) {
            float2 gv = upk(g2[h]);
            float2 ov = *(const float2*)&gbuf[h * DD + dp];
            atomicAdd(&d_G[(b * HH + h) * DD + dp + 0],
                      (gv.x + ov.x) * (1.f / (float)NN));
            atomicAdd(&d_G[(b * HH + h) * DD + dp + 1],
                      (gv.y + ov.y) * (1.f / (float)NN));
        }
    }
}

// ---------------- kernel 4: head proj, weight-reuse over batch -------------
__global__ __launch_bounds__(256) void head_kernel(
    const float* __restrict__ lin_w, const float* __restrict__ lin_b) {
    const int h = blockIdx.x, dc = blockIdx.y;
    const int d0 = dc * 16;
    const int tid = threadIdx.x;
    const int k = tid & 127, half = tid >> 7;
    __shared__ float Gs[BB][16];
    __shared__ float Ws[BB];
    if (tid < BB * 16)
        Gs[tid >> 4][tid & 15] = d_G[((tid >> 4) * HH + h) * DD + d0 + (tid & 15)];
    if (tid < BB) Ws[tid] = d_Wsum[tid * HH + h];
    __syncthreads();

    float acc[BB];
    if (dc == 0 && half == 0) {
        float lb = lin_b[h * KK + k];
#pragma unroll
        for (int b = 0; b < BB; b++) acc[b] = Ws[b] * lb;
    } else {
#pragma unroll
        for (int b = 0; b < BB; b++) acc[b] = 0.f;
    }
#pragma unroll
    for (int dd = 0; dd < 8; dd++) {
        int d = d0 + half * 8 + dd;
        float lw = lin_w[((size_t)h * DD + d) * KK + k];
#pragma unroll
        for (int b = 0; b < BB; b++)
            acc[b] = fmaf(Gs[b][half * 8 + dd], lw, acc[b]);
    }
#pragma unroll
    for (int b = 0; b < BB; b++)
        atomicAdd(&d_head[b * DD + h * KK + k], acc[b]);
}

// ---------------- kernel 5: final proj, weight-reuse over batch ------------
__global__ __launch_bounds__(256) void final_kernel(
    const float* __restrict__ final_w) {
    const int j0 = blockIdx.x * 128, i0 = blockIdx.y * 16;
    const int tid = threadIdx.x;
    const int j = j0 + (tid & 127), half = tid >> 7;
    __shared__ float hs[BB][16];
    if (tid < BB * 16)
        hs[tid >> 4][tid & 15] = d_head[(tid >> 4) * DD + i0 + (tid & 15)];
    __syncthreads();

    float acc[BB];
#pragma unroll
    for (int b = 0; b < BB; b++) acc[b] = 0.f;
#pragma unroll
    for (int ii = 0; ii < 8; ii++) {
        int i = i0 + half * 8 + ii;
        float fw = final_w[(size_t)i * DD + j];
#pragma unroll
        for (int b = 0; b < BB; b++)
            acc[b] = fmaf(hs[b][half * 8 + ii], fw, acc[b]);
    }
#pragma unroll
    for (int b = 0; b < BB; b++)
        atomicAdd(&d_o2[b * DD + j], acc[b]);
}

// ---------------- kernel 6: fc logits (relu applied on read) ---------------
__global__ __launch_bounds__(128) void fc_kernel(
    const float* __restrict__ fc_w, const float* __restrict__ fc_b,
    float* __restrict__ out) {
    const int b = blockIdx.x;
    const int tid = threadIdx.x;
    const int wid = tid >> 5, lane = tid & 31;
    __shared__ float os[DD];
    for (int i = tid; i < DD; i += 128)
        os[i] = fmaxf(d_o2[b * DD + i], 0.f);
    __syncthreads();
    if (wid < LL) {
        float acc = 0.f;
#pragma unroll 4
        for (int i = lane; i < DD; i += 32)
            acc = fmaf(os[i], fc_w[i * LL + wid], acc);
#pragma unroll
        for (int off = 16; off; off >>= 1)
            acc += __shfl_xor_sync(0xffffffffu, acc, off);
        if (lane == 0) out[b * LL + wid] = acc + fc_b[wid];
    }
}

// ---------------- launcher ---------------------------------------------------
extern "C" void kernel_launch(void* const* d_in, const int* in_sizes, int n_in,
                              void* d_out, int out_size) {
    const float* word    = (const float*)d_in[0];
    const float* rel     = (const float*)d_in[1];
    const float* mask    = (const float*)d_in[2];
    const float* Wn_w    = (const float*)d_in[3];
    const float* Wn_b    = (const float*)d_in[4];
    const float* Wr_w    = (const float*)d_in[5];
    const float* Wr_b    = (const float*)d_in[6];
    const float* lin_w   = (const float*)d_in[7];
    const float* lin_b   = (const float*)d_in[8];
    const float* score_w = (const float*)d_in[9];
    const float* score_b = (const float*)d_in[10];
    const float* final_w = (const float*)d_in[11];
    const float* final_b = (const float*)d_in[12];
    const float* fc_w    = (const float*)d_in[13];
    const float* fc_b    = (const float*)d_in[14];
    float* out = (float*)d_out;

    conv_init_kernel<<<192, 256>>>(word, rel, Wn_w, Wr_w, lin_w, lin_b,
                                   score_w, score_b, final_b);

    cudaFuncSetAttribute(gemm_wmma_kernel,
                         cudaFuncAttributeMaxDynamicSharedMemorySize, GSM_BYTES);
    gemm_wmma_kernel<<<dim3(8, 48), 256, GSM_BYTES>>>(Wn_b, Wr_b);

    const int smem_bytes =
        (MM * DD + AT_NB * DD + AT_NB * MM * HH * 2 + HH * DD + 64) * 4;
    cudaFuncSetAttribute(attn_kernel,
                         cudaFuncAttributeMaxDynamicSharedMemorySize, smem_bytes);
    attn_kernel<<<dim3(NN / AT_NB, BB), 512, smem_bytes>>>(mask);

    head_kernel<<<dim3(HH, 32), 256>>>(lin_w, lin_b);
    final_kernel<<<dim3(4, 32), 256>>>(final_w);
    fc_kernel<<<BB, 128>>>(fc_w, fc_b, out);
}